// round 17
// baseline (speedup 1.0000x reference)
#include <cuda_runtime.h>
#include <cuda_bf16.h>

#define TT 512
#define LL 62
#define KK 64
#define GG 8
#define FULLM 0xffffffffu

__device__ int      g_rank2batch[1024];
__device__ unsigned g_Ebf[KK][32];  // [col j][pair p] = bf16x2(e^tr[2p][j], e^tr[2p+1][j])

// Counting-sort batches by seq_len; build exp(trans) table; zero output.
__global__ __launch_bounds__(1024) void prep_kernel(
    const int* __restrict__ seq_len, int B,
    const float* __restrict__ trans, float* __restrict__ out)
{
    __shared__ int scan_s[1024];
    __shared__ int cnt[1024];
    const int tid = threadIdx.x;

    if (tid == 0) out[0] = 0.0f;

    // E table: rows 62,63 of trans are -10000 -> exp = exactly 0.
    for (int i = tid; i < KK * 32; i += 1024) {
        const int jj = i >> 5, p = i & 31;
        __nv_bfloat162 e = __floats2bfloat162_rn(
            __expf(trans[(2 * p) * KK + jj]),
            __expf(trans[(2 * p + 1) * KK + jj]));
        g_Ebf[jj][p] = *reinterpret_cast<unsigned*>(&e);
    }

    scan_s[tid] = 0;
    cnt[tid]    = 0;
    __syncthreads();

    int v = -1;
    if (tid < B) {
        v = min(max(seq_len[tid], 0), 1023);
        atomicAdd(&scan_s[v], 1);
    }
    __syncthreads();

    #pragma unroll
    for (int off = 1; off < 1024; off <<= 1) {
        int x = scan_s[tid];
        if (tid >= off) x += scan_s[tid - off];
        __syncthreads();
        scan_s[tid] = x;
        __syncthreads();
    }

    if (v >= 0) {
        const int base = (v > 0) ? scan_s[v - 1] : 0;
        const int r = base + atomicAdd(&cnt[v], 1);
        g_rank2batch[r] = tid;
    }
}

__device__ __forceinline__ __nv_bfloat162 u32_as_bf2(unsigned int v) {
    __nv_bfloat162 r;
    *reinterpret_cast<unsigned int*>(&r) = v;
    return r;
}

// dot_j = sum_{k=0}^{63} u[k] * E[k][j]; u bf16 in smem (broadcast LDS.128),
// E column j as bf16x2 register pairs. Rows 62,63 of E are exactly 0.
__device__ __forceinline__ float dot64h(const __nv_bfloat16* __restrict__ ubuf,
                                        const __nv_bfloat162* __restrict__ Epk) {
    const uint4* up = reinterpret_cast<const uint4*>(ubuf);
    __nv_bfloat162 z; *reinterpret_cast<unsigned int*>(&z) = 0u;
    __nv_bfloat162 a0 = z, a1 = z, a2 = z, a3 = z;
    #pragma unroll
    for (int q = 0; q < 8; ++q) {
        uint4 v = up[q];
        a0 = __hfma2(u32_as_bf2(v.x), Epk[4 * q + 0], a0);
        a1 = __hfma2(u32_as_bf2(v.y), Epk[4 * q + 1], a1);
        a2 = __hfma2(u32_as_bf2(v.z), Epk[4 * q + 2], a2);
        a3 = __hfma2(u32_as_bf2(v.w), Epk[4 * q + 3], a3);
    }
    __nv_bfloat162 s = __hadd2(__hadd2(a0, a1), __hadd2(a2, a3));
    float2 f = __bfloat1622float2(s);
    return f.x + f.y;
}

__global__ __launch_bounds__(128) void crf_pair_kernel(
    const float* __restrict__ pred,      // [B, T, L]
    const int*   __restrict__ ref,       // [B, T]
    const int*   __restrict__ seq_len,   // [B]
    const float* __restrict__ trans,     // [K, K]  (gold score only)
    float* __restrict__ out)
{
    // snake-balanced rank over 512 pair-blocks (pairs of adjacent sorted
    // ranks -> the two batches in a block have near-equal seq_len).
    const int s_ = blockIdx.x % 148;
    const int g_ = blockIdx.x / 148;
    int idx = g_ * 148 + ((g_ & 1) ? (147 - s_) : s_);
    if (idx >= 512) idx = blockIdx.x;

    const int tid  = threadIdx.x;
    const int j    = tid & 63;           // state column within my batch
    const int half = tid >> 6;           // which batch of the pair
    const int lane = tid & 31;
    const int wid  = tid >> 5;

    const int b = g_rank2batch[2 * idx + half];

    __shared__ __align__(16) __nv_bfloat16 u_sh[2][2][KK]; // [half][buf][state]
    __shared__ int   sls[2];
    __shared__ float red[4], red2[4];

    const float* predb = pred + (size_t)b * TT * LL;
    const int*   refb  = ref  + (size_t)b * TT;
    const int    sl    = seq_len[b];

    if (j == 0) sls[half] = sl;

    // E column j from the precomputed table: 8 LDG.128 (L2-resident, 8 KB)
    __nv_bfloat162 Epk[32];
    {
        const uint4* Eg = reinterpret_cast<const uint4*>(&g_Ebf[j][0]);
        #pragma unroll
        for (int q = 0; q < 8; ++q) {
            const uint4 v = __ldg(&Eg[q]);
            Epk[4 * q + 0] = u32_as_bf2(v.x);
            Epk[4 * q + 1] = u32_as_bf2(v.y);
            Epk[4 * q + 2] = u32_as_bf2(v.z);
            Epk[4 * q + 3] = u32_as_bf2(v.w);
        }
    }

    // u = exp(alpha - c); labels 1 at c = -1000, start/end 0.
    const bool is_lab = (j < LL);
    float c = -1000.0f;
    u_sh[half][0][j] = __float2bfloat16(is_lab ? 1.0f : 0.0f);
    int cur = 0;

    __syncthreads();
    const int smax = max(sls[0], sls[1]);   // common loop bound (≈ sl: sorted pair)

    // eobs pipeline, one 8-step group ahead (exp at prefetch, off the chain)
    float eA[GG], eB[GG];
    #pragma unroll
    for (int i = 0; i < GG; ++i)
        eA[i] = is_lab ? __expf(__ldg(&predb[i * LL + j])) : 0.0f;

    int s = 1;
    while (s + GG <= smax + 1) {             // steps s..s+7
        #pragma unroll
        for (int i = 0; i < GG; ++i) {       // prefetch steps s+8..s+15
            const int row = s + GG - 1 + i;
            eB[i] = (is_lab && row < TT) ? __expf(__ldg(&predb[row * LL + j]))
                                         : 0.0f;
        }
        #pragma unroll
        for (int i = 0; i < GG; ++i) {
            __syncthreads();                 // one barrier serves both batches
            const bool act = (s + i) <= sl;  // uniform within the half
            if (act) {
                float sc = eA[i];
                if (((i & 3) == 0) && !(i == 0 && s == 1)) {  // renorm / 4 steps
                    const float u0 = __bfloat162float(u_sh[half][cur][0]);
                    sc *= __frcp_rn(u0);
                    c += __logf(u0);
                }
                const float d = dot64h(u_sh[half][cur], Epk);
                u_sh[half][cur ^ 1][j] = __float2bfloat16(sc * d);
            }
            cur ^= 1;
        }
        #pragma unroll
        for (int i = 0; i < GG; ++i) eA[i] = eB[i];
        s += GG;
    }

    const int rem = smax + 1 - s;            // 0..GG-1 remaining steps
    #pragma unroll
    for (int i = 0; i < GG - 1; ++i) {
        if (i >= rem) break;
        __syncthreads();
        const bool act = (s + i) <= sl;
        if (act) {
            float sc = eA[i];
            if (((i & 3) == 0) && !(i == 0 && s == 1)) {
                const float u0 = __bfloat162float(u_sh[half][cur][0]);
                sc *= __frcp_rn(u0);
                c += __logf(u0);
            }
            const float d = dot64h(u_sh[half][cur], Epk);
            u_sh[half][cur ^ 1][j] = __float2bfloat16(sc * d);
        }
        cur ^= 1;
    }
    __syncthreads();

    // ---- boundary step (sl+1) in log domain; frozen u in buffer sl&1 ----
    const float dB = dot64h(u_sh[half][sl & 1], Epk);
    float obs_b;
    if (is_lab)
        obs_b = ((sl < TT) ? predb[sl * LL + j] : 0.0f) - 1000.0f;
    else
        obs_b = (j == LL) ? -1000.0f : 0.0f;
    const float alpha_fin = obs_b + c + __logf(dB);

    // ---- logsumexp over my batch's 64 columns (2 warps per half) ----
    float v = alpha_fin;
    #pragma unroll
    for (int off = 16; off; off >>= 1)
        v = fmaxf(v, __shfl_xor_sync(FULLM, v, off));
    if (lane == 0) red[wid] = v;
    __syncthreads();
    const float M = fmaxf(red[2 * half], red[2 * half + 1]);

    float e = __expf(alpha_fin - M);
    #pragma unroll
    for (int off = 16; off; off >>= 1)
        e += __shfl_xor_sync(FULLM, e, off);
    if (lane == 0) red2[wid] = e;
    __syncthreads();
    const float lse = M + __logf(red2[2 * half] + red2[2 * half + 1]);

    // ---- gold score, exact fp32, 64 threads per batch ----
    float gold = 0.0f;
    for (int t = j; t < sl; t += KK)
        gold += __ldg(&predb[t * LL + __ldg(&refb[t])]);
    for (int t = j; t <= sl; t += KK) {
        const int from = (t == 0)  ? LL       : __ldg(&refb[t - 1]);
        const int to   = (t == sl) ? (LL + 1) : __ldg(&refb[t]);
        gold += __ldg(&trans[from * KK + to]);
    }
    #pragma unroll
    for (int off = 16; off; off >>= 1)
        gold += __shfl_xor_sync(FULLM, gold, off);
    __syncthreads();                          // red free for reuse
    if (lane == 0) red[wid] = gold;
    __syncthreads();
    const float gold_total = red[2 * half] + red[2 * half + 1];

    if (j == 0)
        atomicAdd(out, lse - gold_total);
}

extern "C" void kernel_launch(void* const* d_in, const int* in_sizes, int n_in,
                              void* d_out, int out_size)
{
    const float* pred    = (const float*)d_in[0];
    const int*   ref     = (const int*)d_in[1];
    const int*   seq_len = (const int*)d_in[2];
    const float* trans   = (const float*)d_in[3];
    float*       out     = (float*)d_out;

    const int B = in_sizes[2];   // 1024

    prep_kernel<<<1, 1024>>>(seq_len, B, trans, out);
    crf_pair_kernel<<<B / 2, 128>>>(pred, ref, seq_len, trans, out);
}